// round 11
// baseline (speedup 1.0000x reference)
#include <cuda_runtime.h>
#include <cuda_bf16.h>

// Problem constants
static constexpr int NB   = 512;   // batch
static constexpr int ND   = 512;   // hidden dim
static constexpr int NL_T = 256;   // time steps
// gates rows = 4*ND = 2048

// ---------------- scratch (__device__ globals; no allocation) ----------------
__device__ float g_h0[2][NB * ND];          // layer0 hidden, ping-pong
__device__ float g_A1[2][NB * 1024];        // layer1 A = [y0_t | h1], ping-pong
__device__ float g_c0[NB * ND];             // layer0 cell
__device__ float g_c1[NB * ND];             // layer1 cell
__device__ unsigned short g_Wp0[2048 * 512];   // packed bf16 W_hh0
__device__ unsigned short g_Wp1[2048 * 1024];  // packed bf16 [W_ih1 | W_hh1]
__device__ float g_b0[2048];                // packed bias (b_ih0+b_hh0)
__device__ float g_b1[2048];                // packed bias (b_ih1+b_hh1)
__device__ float g_Opart[NL_T * 16 * NB];   // per-(step,dblock) output partials

// packed row -> original gate row. Packed layout: for dblock j (32 d-cols),
// 128 consecutive rows = [i(32), f(32), g(32), o(32)] for d = j*32..j*32+31.
__device__ __forceinline__ int orig_row(int pr) {
    int j = pr >> 7, chunk = (pr >> 5) & 3, r = pr & 31;
    return chunk * 512 + j * 32 + r;
}

__device__ __forceinline__ unsigned f2tf(float f) {
    unsigned r;
    asm("cvt.rna.tf32.f32 %0, %1;" : "=r"(r) : "f"(f));
    return r;
}
__device__ __forceinline__ float sigm(float x) { return 1.0f / (1.0f + __expf(-x)); }

__device__ __forceinline__ void cpa16(void* s, const void* g) {
    unsigned sa = (unsigned)__cvta_generic_to_shared(s);
    asm volatile("cp.async.cg.shared.global [%0], [%1], 16;" :: "r"(sa), "l"(g));
}

// ---------------- weight/bias pack + bf16 convert ----------------
__global__ void pack_weights(const float* __restrict__ Whh0,
                             const float* __restrict__ Wih1,
                             const float* __restrict__ Whh1,
                             const float* __restrict__ bih0,
                             const float* __restrict__ bhh0,
                             const float* __restrict__ bih1,
                             const float* __restrict__ bhh1) {
    int idx = blockIdx.x * blockDim.x + threadIdx.x;
    const int T0 = 2048 * 512;
    const int T1 = 2048 * 1024;
    if (idx < T0) {
        int pr = idx >> 9, k = idx & 511;
        int orow = orig_row(pr);
        __nv_bfloat16 v = __float2bfloat16(Whh0[orow * 512 + k]);
        g_Wp0[idx] = *reinterpret_cast<unsigned short*>(&v);
        if (idx < 2048) {
            int o2 = orig_row(idx);
            g_b0[idx] = bih0[o2] + bhh0[o2];
            g_b1[idx] = bih1[o2] + bhh1[o2];
        }
    } else if (idx < T0 + T1) {
        int i2 = idx - T0;
        int pr = i2 >> 10, k = i2 & 1023;
        int orow = orig_row(pr);
        float f = (k < 512) ? Wih1[orow * 512 + k] : Whh1[orow * 512 + (k - 512)];
        __nv_bfloat16 v = __float2bfloat16(f);
        g_Wp1[i2] = *reinterpret_cast<unsigned short*>(&v);
    }
}

// ---------------- init: C(512x1024) = tanh(c_star @ Wt^T + bias) ----------------
// NOTE: reshape (B,2D)->(NL,B,D) is interleaving:
//   output element (rb, n) belongs to layer = rb/256, b = (rb%256)*2 + (n>=512), d = n%512
__global__ void __launch_bounds__(256) init_gemm(const float* __restrict__ cstar,
                                                 const float* __restrict__ Wt,
                                                 const float* __restrict__ bias,
                                                 int is_h) {
    __shared__ float As[64][20];
    __shared__ float Bs[64][20];
    int tid = threadIdx.x;
    int rb0 = blockIdx.x * 64, n0 = blockIdx.y * 64;
    int tx = tid & 15, ty = tid >> 4;
    float acc[4][4];
#pragma unroll
    for (int i = 0; i < 4; i++)
#pragma unroll
        for (int j = 0; j < 4; j++) acc[i][j] = 0.f;

    int lr = tid >> 2, lc = (tid & 3) * 4;
    for (int k0 = 0; k0 < 512; k0 += 16) {
        *(float4*)&As[lr][lc] = *(const float4*)&cstar[(rb0 + lr) * 512 + k0 + lc];
        *(float4*)&Bs[lr][lc] = *(const float4*)&Wt[(n0 + lr) * 512 + k0 + lc];
        __syncthreads();
#pragma unroll
        for (int kk = 0; kk < 16; kk++) {
            float a[4], bv[4];
#pragma unroll
            for (int i = 0; i < 4; i++) a[i] = As[ty + 16 * i][kk];
#pragma unroll
            for (int j = 0; j < 4; j++) bv[j] = Bs[tx + 16 * j][kk];
#pragma unroll
            for (int i = 0; i < 4; i++)
#pragma unroll
                for (int j = 0; j < 4; j++) acc[i][j] += a[i] * bv[j];
        }
        __syncthreads();
    }
#pragma unroll
    for (int i = 0; i < 4; i++) {
#pragma unroll
        for (int j = 0; j < 4; j++) {
            int rb = rb0 + ty + 16 * i;
            int n = n0 + tx + 16 * j;
            float v = tanhf(acc[i][j] + bias[n]);
            int b = ((rb & 255) << 1) + (n >> 9);
            int d = n & 511;
            if (is_h) {
                if (rb < 256) g_h0[0][b * 512 + d] = v;                // layer0 h init
                else          g_A1[0][b * 1024 + 512 + d] = v;         // layer1 h init
            } else {
                if (rb < 256) g_c0[b * 512 + d] = v;
                else          g_c1[b * 512 + d] = v;
            }
        }
    }
}

// ---------------- fused LSTM step: tf32 MMA GEMM + pointwise ----------------
// Block computes 64 batch rows x (4 gates x 32 d-cols). Grid (8, 16), 256 threads.
template <int K, int LAYER>
__global__ void __launch_bounds__(256) lstm_step(int parity, int step,
                                                 const float* __restrict__ ow) {
    __shared__ __align__(16) char smem_raw[38912];
    float* AshF = (float*)smem_raw;                              // [2][64][36]
    unsigned short* BshU = (unsigned short*)(smem_raw + 18432);  // [2][128][40]

    const float* A = (LAYER == 0) ? g_h0[parity] : g_A1[parity];
    const unsigned short* W = (LAYER == 0) ? g_Wp0 : g_Wp1;
    const float* biasp = ((LAYER == 0) ? g_b0 : g_b1) + blockIdx.y * 128;
    float* cb = (LAYER == 0) ? g_c0 : g_c1;

    const int tid = threadIdx.x;
    const int lane = tid & 31, wid = tid >> 5;
    const int mrow0 = blockIdx.x * 64;
    const int wrow0 = blockIdx.y * 128;
    const int mBase = (wid & 3) * 16;
    const int nBase = (wid >> 2) * 64;
    const int g = lane >> 2, tg = lane & 3;
    const int NKC = K / 32;

    float acc[8][4];
#pragma unroll
    for (int i = 0; i < 8; i++)
#pragma unroll
        for (int j = 0; j < 4; j++) acc[i][j] = 0.f;

    // cp.async loader for one 32-wide K chunk
    auto load_chunk = [&](int buf, int kb) {
        int t2 = tid * 2;
#pragma unroll
        for (int i = 0; i < 2; i++) {
            int id = t2 + i;
            int r = id >> 3, s = id & 7;  // A: 64 rows x 8 segs of 16B
            cpa16(&AshF[buf * 2304 + r * 36 + s * 4], &A[(mrow0 + r) * K + kb + s * 4]);
        }
#pragma unroll
        for (int i = 0; i < 2; i++) {
            int id = t2 + i;
            int r = id >> 2, s = id & 3;  // B: 128 rows x 4 segs of 16B (bf16)
            cpa16(&BshU[buf * 5120 + r * 40 + s * 8], &W[(wrow0 + r) * K + kb + s * 8]);
        }
        asm volatile("cp.async.commit_group;");
    };

    load_chunk(0, 0);

    for (int kc = 0; kc < NKC; kc++) {
        if (kc + 1 < NKC) {
            load_chunk((kc + 1) & 1, (kc + 1) * 32);
            asm volatile("cp.async.wait_group 1;");
        } else {
            asm volatile("cp.async.wait_group 0;");
        }
        __syncthreads();
        const float* Ab = &AshF[(kc & 1) * 2304];
        const unsigned short* Bb = &BshU[(kc & 1) * 5120];
#pragma unroll
        for (int k8 = 0; k8 < 4; k8++) {
            unsigned a0 = f2tf(Ab[(mBase + g) * 36 + k8 * 8 + tg]);
            unsigned a1 = f2tf(Ab[(mBase + g + 8) * 36 + k8 * 8 + tg]);
            unsigned a2 = f2tf(Ab[(mBase + g) * 36 + k8 * 8 + tg + 4]);
            unsigned a3 = f2tf(Ab[(mBase + g + 8) * 36 + k8 * 8 + tg + 4]);
#pragma unroll
            for (int nn = 0; nn < 8; nn++) {
                int n = nBase + nn * 8 + g;
                unsigned b0 = ((unsigned)Bb[n * 40 + k8 * 8 + tg]) << 16;      // bf16->f32 exact
                unsigned b1 = ((unsigned)Bb[n * 40 + k8 * 8 + tg + 4]) << 16;
                asm volatile(
                    "mma.sync.aligned.m16n8k8.row.col.f32.tf32.tf32.f32 "
                    "{%0,%1,%2,%3},{%4,%5,%6,%7},{%8,%9},{%0,%1,%2,%3};"
                    : "+f"(acc[nn][0]), "+f"(acc[nn][1]), "+f"(acc[nn][2]), "+f"(acc[nn][3])
                    : "r"(a0), "r"(a1), "r"(a2), "r"(a3), "r"(b0), "r"(b1));
            }
        }
        __syncthreads();
    }

    // Epilogue: stage C tile (64 x 128) in smem (overlays GEMM buffers)
    float* Csh = (float*)smem_raw;  // [64][132]
#pragma unroll
    for (int nn = 0; nn < 8; nn++) {
        int col = nBase + nn * 8 + tg * 2;
        Csh[(mBase + g) * 132 + col] = acc[nn][0];
        Csh[(mBase + g) * 132 + col + 1] = acc[nn][1];
        Csh[(mBase + g + 8) * 132 + col] = acc[nn][2];
        Csh[(mBase + g + 8) * 132 + col + 1] = acc[nn][3];
    }
    __syncthreads();

    // Pointwise LSTM update: thread -> (row r, 8 consecutive d-cols)
    int r = tid >> 2;
    int jb = (tid & 3) * 8;
    int b = mrow0 + r;
    float part = 0.f;
    float* h0n = g_h0[parity ^ 1];
    float* a1c = g_A1[parity];
    float* a1n = g_A1[parity ^ 1];
#pragma unroll
    for (int jj = 0; jj < 8; jj++) {
        int j = jb + jj;
        float iv = Csh[r * 132 + j] + biasp[j];
        float fv = Csh[r * 132 + 32 + j] + biasp[32 + j];
        float gv = Csh[r * 132 + 64 + j] + biasp[64 + j];
        float ovv = Csh[r * 132 + 96 + j] + biasp[96 + j];
        int d = blockIdx.y * 32 + j;
        float cold = cb[b * 512 + d];
        float cn = sigm(fv) * cold + sigm(iv) * tanhf(gv);
        float hn = sigm(ovv) * tanhf(cn);
        cb[b * 512 + d] = cn;
        if (LAYER == 0) {
            h0n[b * 512 + d] = hn;        // next-step layer0 A
            a1c[b * 1024 + d] = hn;       // y0_t into this step's layer1 A
        } else {
            a1n[b * 1024 + 512 + d] = hn; // h1_t into next step's layer1 A
            part += hn * ow[d];           // output projection partial
        }
    }
    if (LAYER == 1) {
        part += __shfl_xor_sync(0xffffffffu, part, 1);
        part += __shfl_xor_sync(0xffffffffu, part, 2);
        if ((tid & 3) == 0)
            g_Opart[(step * 16 + blockIdx.y) * 512 + b] = part;
    }
}

// ---------------- final: reduce partials, add out_b, split recon/pred ----------------
__global__ void final_proj(const float* __restrict__ out_b, float* __restrict__ out) {
    int idx = blockIdx.x * blockDim.x + threadIdx.x;
    if (idx >= NB * NL_T) return;
    int t = idx >> 9;   // 0..255
    int b = idx & 511;  // 0..511
    float s = out_b[0];
#pragma unroll
    for (int j = 0; j < 16; j++) s += g_Opart[(t * 16 + j) * 512 + b];
    if (t < NL_T - 1)
        out[b * (NL_T - 1) + t] = s;       // recon (B, L-1)
    else
        out[NB * (NL_T - 1) + b] = s;      // pred (B,)
}

// ---------------- launch ----------------
extern "C" void kernel_launch(void* const* d_in, const int* in_sizes, int n_in,
                              void* d_out, int out_size) {
    (void)in_sizes; (void)n_in; (void)out_size;
    const float* c_star   = (const float*)d_in[0];
    const float* init_h_w = (const float*)d_in[1];
    const float* init_h_b = (const float*)d_in[2];
    const float* init_c_w = (const float*)d_in[3];
    const float* init_c_b = (const float*)d_in[4];
    // d_in[5] = W_ih0: unused (layer0 input term is pure bias in the reference)
    const float* W_hh0 = (const float*)d_in[6];
    const float* b_ih0 = (const float*)d_in[7];
    const float* b_hh0 = (const float*)d_in[8];
    const float* W_ih1 = (const float*)d_in[9];
    const float* W_hh1 = (const float*)d_in[10];
    const float* b_ih1 = (const float*)d_in[11];
    const float* b_hh1 = (const float*)d_in[12];
    const float* out_w = (const float*)d_in[13];
    const float* out_b = (const float*)d_in[14];
    float* out = (float*)d_out;

    // 1) pack weights to bf16 + fuse biases (3,145,728 items)
    pack_weights<<<12288, 256>>>(W_hh0, W_ih1, W_hh1, b_ih0, b_hh0, b_ih1, b_hh1);

    // 2) initial states (handles the interleaving reshape)
    dim3 ig(8, 16);
    init_gemm<<<ig, 256>>>(c_star, init_h_w, init_h_b, 1);
    init_gemm<<<ig, 256>>>(c_star, init_c_w, init_c_b, 0);

    // 3) recurrence: 256 steps x 2 layers
    dim3 sg(8, 16);
    for (int t = 0; t < NL_T; t++) {
        lstm_step<512, 0><<<sg, 256>>>(t & 1, t, out_w);
        lstm_step<1024, 1><<<sg, 256>>>(t & 1, t, out_w);
    }

    // 4) output reduction + layout
    final_proj<<<512, 256>>>(out_b, out);
}

// round 12
// speedup vs baseline: 1.0036x; 1.0036x over previous
#include <cuda_runtime.h>
#include <cuda_bf16.h>

// Problem constants
static constexpr int NB   = 512;   // batch
static constexpr int ND   = 512;   // hidden dim
static constexpr int NL_T = 256;   // time steps
// gates rows = 4*ND = 2048

// ---------------- scratch (__device__ globals; no allocation) ----------------
__device__ float g_h0[2][NB * ND];          // layer0 hidden, ping-pong
__device__ float g_A1[2][NB * 1024];        // layer1 A = [y0_t | h1], ping-pong
__device__ float g_c0[NB * ND];             // layer0 cell
__device__ float g_c1[NB * ND];             // layer1 cell
__device__ unsigned short g_Wp0[2048 * 512];   // packed bf16 W_hh0
__device__ unsigned short g_Wp1[2048 * 1024];  // packed bf16 [W_ih1 | W_hh1]
__device__ float g_b0[2048];                // packed bias (b_ih0+b_hh0)
__device__ float g_b1[2048];                // packed bias (b_ih1+b_hh1)
__device__ float g_Opart[NL_T * 16 * NB];   // per-(step,dblock) output partials

// packed row -> original gate row. Packed layout: for dblock j (32 d-cols),
// 128 consecutive rows = [i(32), f(32), g(32), o(32)] for d = j*32..j*32+31.
__device__ __forceinline__ int orig_row(int pr) {
    int j = pr >> 7, chunk = (pr >> 5) & 3, r = pr & 31;
    return chunk * 512 + j * 32 + r;
}

__device__ __forceinline__ unsigned f2tf(float f) {
    unsigned r;
    asm("cvt.rna.tf32.f32 %0, %1;" : "=r"(r) : "f"(f));
    return r;
}
__device__ __forceinline__ float sigm(float x) { return 1.0f / (1.0f + __expf(-x)); }

__device__ __forceinline__ void cpa16(void* s, const void* g) {
    unsigned sa = (unsigned)__cvta_generic_to_shared(s);
    asm volatile("cp.async.cg.shared.global [%0], [%1], 16;" :: "r"(sa), "l"(g));
}

// ---------------- weight/bias pack + bf16 convert ----------------
__global__ void pack_weights(const float* __restrict__ Whh0,
                             const float* __restrict__ Wih1,
                             const float* __restrict__ Whh1,
                             const float* __restrict__ bih0,
                             const float* __restrict__ bhh0,
                             const float* __restrict__ bih1,
                             const float* __restrict__ bhh1) {
    int idx = blockIdx.x * blockDim.x + threadIdx.x;
    const int T0 = 2048 * 512;
    const int T1 = 2048 * 1024;
    if (idx < T0) {
        int pr = idx >> 9, k = idx & 511;
        int orow = orig_row(pr);
        __nv_bfloat16 v = __float2bfloat16(Whh0[orow * 512 + k]);
        g_Wp0[idx] = *reinterpret_cast<unsigned short*>(&v);
        if (idx < 2048) {
            int o2 = orig_row(idx);
            g_b0[idx] = bih0[o2] + bhh0[o2];
            g_b1[idx] = bih1[o2] + bhh1[o2];
        }
    } else if (idx < T0 + T1) {
        int i2 = idx - T0;
        int pr = i2 >> 10, k = i2 & 1023;
        int orow = orig_row(pr);
        float f = (k < 512) ? Wih1[orow * 512 + k] : Whh1[orow * 512 + (k - 512)];
        __nv_bfloat16 v = __float2bfloat16(f);
        g_Wp1[i2] = *reinterpret_cast<unsigned short*>(&v);
    }
}

// ---------------- init: C(512x1024) = tanh(c_star @ Wt^T + bias) ----------------
// NOTE: reshape (B,2D)->(NL,B,D) is interleaving:
//   output element (rb, n) belongs to layer = rb/256, b = (rb%256)*2 + (n>=512), d = n%512
__global__ void __launch_bounds__(256) init_gemm(const float* __restrict__ cstar,
                                                 const float* __restrict__ Wt,
                                                 const float* __restrict__ bias,
                                                 int is_h) {
    __shared__ float As[64][20];
    __shared__ float Bs[64][20];
    int tid = threadIdx.x;
    int rb0 = blockIdx.x * 64, n0 = blockIdx.y * 64;
    int tx = tid & 15, ty = tid >> 4;
    float acc[4][4];
#pragma unroll
    for (int i = 0; i < 4; i++)
#pragma unroll
        for (int j = 0; j < 4; j++) acc[i][j] = 0.f;

    int lr = tid >> 2, lc = (tid & 3) * 4;
    for (int k0 = 0; k0 < 512; k0 += 16) {
        *(float4*)&As[lr][lc] = *(const float4*)&cstar[(rb0 + lr) * 512 + k0 + lc];
        *(float4*)&Bs[lr][lc] = *(const float4*)&Wt[(n0 + lr) * 512 + k0 + lc];
        __syncthreads();
#pragma unroll
        for (int kk = 0; kk < 16; kk++) {
            float a[4], bv[4];
#pragma unroll
            for (int i = 0; i < 4; i++) a[i] = As[ty + 16 * i][kk];
#pragma unroll
            for (int j = 0; j < 4; j++) bv[j] = Bs[tx + 16 * j][kk];
#pragma unroll
            for (int i = 0; i < 4; i++)
#pragma unroll
                for (int j = 0; j < 4; j++) acc[i][j] += a[i] * bv[j];
        }
        __syncthreads();
    }
#pragma unroll
    for (int i = 0; i < 4; i++) {
#pragma unroll
        for (int j = 0; j < 4; j++) {
            int rb = rb0 + ty + 16 * i;
            int n = n0 + tx + 16 * j;
            float v = tanhf(acc[i][j] + bias[n]);
            int b = ((rb & 255) << 1) + (n >> 9);
            int d = n & 511;
            if (is_h) {
                if (rb < 256) g_h0[0][b * 512 + d] = v;                // layer0 h init
                else          g_A1[0][b * 1024 + 512 + d] = v;         // layer1 h init
            } else {
                if (rb < 256) g_c0[b * 512 + d] = v;
                else          g_c1[b * 512 + d] = v;
            }
        }
    }
}

// ---------------- fused LSTM step: tf32 MMA GEMM + pointwise ----------------
// Block computes 64 batch rows x (4 gates x 32 d-cols). Grid (8, 16), 256 threads.
template <int K, int LAYER>
__global__ void __launch_bounds__(256) lstm_step(int parity, int step,
                                                 const float* __restrict__ ow) {
    __shared__ __align__(16) char smem_raw[38912];
    float* AshF = (float*)smem_raw;                              // [2][64][36]
    unsigned short* BshU = (unsigned short*)(smem_raw + 18432);  // [2][128][40]

    const float* A = (LAYER == 0) ? g_h0[parity] : g_A1[parity];
    const unsigned short* W = (LAYER == 0) ? g_Wp0 : g_Wp1;
    const float* biasp = ((LAYER == 0) ? g_b0 : g_b1) + blockIdx.y * 128;
    float* cb = (LAYER == 0) ? g_c0 : g_c1;

    const int tid = threadIdx.x;
    const int lane = tid & 31, wid = tid >> 5;
    const int mrow0 = blockIdx.x * 64;
    const int wrow0 = blockIdx.y * 128;
    const int mBase = (wid & 3) * 16;
    const int nBase = (wid >> 2) * 64;
    const int g = lane >> 2, tg = lane & 3;
    const int NKC = K / 32;

    float acc[8][4];
#pragma unroll
    for (int i = 0; i < 8; i++)
#pragma unroll
        for (int j = 0; j < 4; j++) acc[i][j] = 0.f;

    // cp.async loader for one 32-wide K chunk
    auto load_chunk = [&](int buf, int kb) {
        int t2 = tid * 2;
#pragma unroll
        for (int i = 0; i < 2; i++) {
            int id = t2 + i;
            int r = id >> 3, s = id & 7;  // A: 64 rows x 8 segs of 16B
            cpa16(&AshF[buf * 2304 + r * 36 + s * 4], &A[(mrow0 + r) * K + kb + s * 4]);
        }
#pragma unroll
        for (int i = 0; i < 2; i++) {
            int id = t2 + i;
            int r = id >> 2, s = id & 3;  // B: 128 rows x 4 segs of 16B (bf16)
            cpa16(&BshU[buf * 5120 + r * 40 + s * 8], &W[(wrow0 + r) * K + kb + s * 8]);
        }
        asm volatile("cp.async.commit_group;");
    };

    load_chunk(0, 0);

    for (int kc = 0; kc < NKC; kc++) {
        if (kc + 1 < NKC) {
            load_chunk((kc + 1) & 1, (kc + 1) * 32);
            asm volatile("cp.async.wait_group 1;");
        } else {
            asm volatile("cp.async.wait_group 0;");
        }
        __syncthreads();
        const float* Ab = &AshF[(kc & 1) * 2304];
        const unsigned short* Bb = &BshU[(kc & 1) * 5120];
#pragma unroll
        for (int k8 = 0; k8 < 4; k8++) {
            unsigned a0 = f2tf(Ab[(mBase + g) * 36 + k8 * 8 + tg]);
            unsigned a1 = f2tf(Ab[(mBase + g + 8) * 36 + k8 * 8 + tg]);
            unsigned a2 = f2tf(Ab[(mBase + g) * 36 + k8 * 8 + tg + 4]);
            unsigned a3 = f2tf(Ab[(mBase + g + 8) * 36 + k8 * 8 + tg + 4]);
#pragma unroll
            for (int nn = 0; nn < 8; nn++) {
                int n = nBase + nn * 8 + g;
                unsigned b0 = ((unsigned)Bb[n * 40 + k8 * 8 + tg]) << 16;      // bf16->f32 exact
                unsigned b1 = ((unsigned)Bb[n * 40 + k8 * 8 + tg + 4]) << 16;
                asm volatile(
                    "mma.sync.aligned.m16n8k8.row.col.f32.tf32.tf32.f32 "
                    "{%0,%1,%2,%3},{%4,%5,%6,%7},{%8,%9},{%0,%1,%2,%3};"
                    : "+f"(acc[nn][0]), "+f"(acc[nn][1]), "+f"(acc[nn][2]), "+f"(acc[nn][3])
                    : "r"(a0), "r"(a1), "r"(a2), "r"(a3), "r"(b0), "r"(b1));
            }
        }
        __syncthreads();
    }

    // Epilogue: stage C tile (64 x 128) in smem (overlays GEMM buffers)
    float* Csh = (float*)smem_raw;  // [64][132]
#pragma unroll
    for (int nn = 0; nn < 8; nn++) {
        int col = nBase + nn * 8 + tg * 2;
        Csh[(mBase + g) * 132 + col] = acc[nn][0];
        Csh[(mBase + g) * 132 + col + 1] = acc[nn][1];
        Csh[(mBase + g + 8) * 132 + col] = acc[nn][2];
        Csh[(mBase + g + 8) * 132 + col + 1] = acc[nn][3];
    }
    __syncthreads();

    // Pointwise LSTM update: thread -> (row r, 8 consecutive d-cols)
    int r = tid >> 2;
    int jb = (tid & 3) * 8;
    int b = mrow0 + r;
    float part = 0.f;
    float* h0n = g_h0[parity ^ 1];
    float* a1c = g_A1[parity];
    float* a1n = g_A1[parity ^ 1];
#pragma unroll
    for (int jj = 0; jj < 8; jj++) {
        int j = jb + jj;
        float iv = Csh[r * 132 + j] + biasp[j];
        float fv = Csh[r * 132 + 32 + j] + biasp[32 + j];
        float gv = Csh[r * 132 + 64 + j] + biasp[64 + j];
        float ovv = Csh[r * 132 + 96 + j] + biasp[96 + j];
        int d = blockIdx.y * 32 + j;
        float cold = cb[b * 512 + d];
        float cn = sigm(fv) * cold + sigm(iv) * tanhf(gv);
        float hn = sigm(ovv) * tanhf(cn);
        cb[b * 512 + d] = cn;
        if (LAYER == 0) {
            h0n[b * 512 + d] = hn;        // next-step layer0 A
            a1c[b * 1024 + d] = hn;       // y0_t into this step's layer1 A
        } else {
            a1n[b * 1024 + 512 + d] = hn; // h1_t into next step's layer1 A
            part += hn * ow[d];           // output projection partial
        }
    }
    if (LAYER == 1) {
        part += __shfl_xor_sync(0xffffffffu, part, 1);
        part += __shfl_xor_sync(0xffffffffu, part, 2);
        if ((tid & 3) == 0)
            g_Opart[(step * 16 + blockIdx.y) * 512 + b] = part;
    }
}

// ---------------- final: reduce partials, add out_b, split recon/pred ----------------
__global__ void final_proj(const float* __restrict__ out_b, float* __restrict__ out) {
    int idx = blockIdx.x * blockDim.x + threadIdx.x;
    if (idx >= NB * NL_T) return;
    int t = idx >> 9;   // 0..255
    int b = idx & 511;  // 0..511
    float s = out_b[0];
#pragma unroll
    for (int j = 0; j < 16; j++) s += g_Opart[(t * 16 + j) * 512 + b];
    if (t < NL_T - 1)
        out[b * (NL_T - 1) + t] = s;       // recon (B, L-1)
    else
        out[NB * (NL_T - 1) + b] = s;      // pred (B,)
}

// ---------------- launch ----------------
extern "C" void kernel_launch(void* const* d_in, const int* in_sizes, int n_in,
                              void* d_out, int out_size) {
    (void)in_sizes; (void)n_in; (void)out_size;
    const float* c_star   = (const float*)d_in[0];
    const float* init_h_w = (const float*)d_in[1];
    const float* init_h_b = (const float*)d_in[2];
    const float* init_c_w = (const float*)d_in[3];
    const float* init_c_b = (const float*)d_in[4];
    // d_in[5] = W_ih0: unused (layer0 input term is pure bias in the reference)
    const float* W_hh0 = (const float*)d_in[6];
    const float* b_ih0 = (const float*)d_in[7];
    const float* b_hh0 = (const float*)d_in[8];
    const float* W_ih1 = (const float*)d_in[9];
    const float* W_hh1 = (const float*)d_in[10];
    const float* b_ih1 = (const float*)d_in[11];
    const float* b_hh1 = (const float*)d_in[12];
    const float* out_w = (const float*)d_in[13];
    const float* out_b = (const float*)d_in[14];
    float* out = (float*)d_out;

    // 1) pack weights to bf16 + fuse biases (3,145,728 items)
    pack_weights<<<12288, 256>>>(W_hh0, W_ih1, W_hh1, b_ih0, b_hh0, b_ih1, b_hh1);

    // 2) initial states (handles the interleaving reshape)
    dim3 ig(8, 16);
    init_gemm<<<ig, 256>>>(c_star, init_h_w, init_h_b, 1);
    init_gemm<<<ig, 256>>>(c_star, init_c_w, init_c_b, 0);

    // 3) recurrence: 256 steps x 2 layers
    dim3 sg(8, 16);
    for (int t = 0; t < NL_T; t++) {
        lstm_step<512, 0><<<sg, 256>>>(t & 1, t, out_w);
        lstm_step<1024, 1><<<sg, 256>>>(t & 1, t, out_w);
    }

    // 4) output reduction + layout
    final_proj<<<512, 256>>>(out_b, out);
}

// round 13
// speedup vs baseline: 2.4171x; 2.4084x over previous
#include <cuda_runtime.h>
#include <cuda_bf16.h>

// ============ sizes ============
// B=512, D=512, L=256, 2 layers. Persistent kernel: 128 blocks x 256 thr,
// block (m0=bid>>5, n0=bid&31): 128 batch rows x 16 d (= 64 packed gate rows).

// smem layout (bytes)
static constexpr int SMEM_BYTES = 230400;
static constexpr int W1_OFF = 65536;    // W0: [0,65536)  64x512 bf16 swizzled
static constexpr int AB_OFF = 196608;   // W1: [65536,196608) 64x1024 bf16
static constexpr int B0_OFF = 229376;   // A dbl buf 2x16384 / C staging 128x64 f32
static constexpr int B1_OFF = 229632;
static constexpr int OW_OFF = 229888;

// ============ device scratch ============
__device__ __nv_bfloat16 g_h0[2][512 * 512];
__device__ __nv_bfloat16 g_A1[2][512 * 1024];   // [y0 | h1]
__device__ float g_c0[512 * 512];
__device__ float g_c1[512 * 512];
__device__ unsigned short g_W0p[32 * 64 * 512];
__device__ unsigned short g_W1p[32 * 64 * 1024];
__device__ float g_b0p[2048];
__device__ float g_b1p[2048];
__device__ float g_Opart[256 * 32 * 512];
__device__ unsigned g_sync;

__device__ __forceinline__ float sigm(float x) {
    return __fdividef(1.0f, 1.0f + __expf(-x));
}
__device__ __forceinline__ float tanh_(float x) {
    return __fdividef(2.0f, 1.0f + __expf(-2.0f * x)) - 1.0f;
}
__device__ __forceinline__ void cpa16(unsigned dst_s, const void* src_g) {
    asm volatile("cp.async.cg.shared.global [%0], [%1], 16;" :: "r"(dst_s), "l"(src_g));
}
__device__ __forceinline__ void mma_bf16(float* c, const unsigned* a,
                                         unsigned b0, unsigned b1) {
    asm volatile(
        "mma.sync.aligned.m16n8k16.row.col.f32.bf16.bf16.f32 "
        "{%0,%1,%2,%3},{%4,%5,%6,%7},{%8,%9},{%0,%1,%2,%3};"
        : "+f"(c[0]), "+f"(c[1]), "+f"(c[2]), "+f"(c[3])
        : "r"(a[0]), "r"(a[1]), "r"(a[2]), "r"(a[3]), "r"(b0), "r"(b1));
}

// ============ weight pack: bf16 + block layout + XOR swizzle ============
// block n (0..31), packed row r (0..63): orig gate row = (r>>4)*512 + n*16 + (r&15).
// bf16 pair-word w (k>>1) stored at w ^ ((r&7)<<2).
__global__ void pack_weights(const float* __restrict__ Whh0,
                             const float* __restrict__ Wih1,
                             const float* __restrict__ Whh1,
                             const float* __restrict__ bih0,
                             const float* __restrict__ bhh0,
                             const float* __restrict__ bih1,
                             const float* __restrict__ bhh1) {
    int idx = blockIdx.x * blockDim.x + threadIdx.x;
    const int T0 = 32 * 64 * 512;
    const int T1 = 32 * 64 * 1024;
    if (idx < T0) {
        int k = idx & 511, r = (idx >> 9) & 63, n = idx >> 15;
        int orow = (r >> 4) * 512 + n * 16 + (r & 15);
        int w = (k >> 1) ^ ((r & 7) << 2);
        __nv_bfloat16 v = __float2bfloat16(Whh0[orow * 512 + k]);
        g_W0p[(n * 64 + r) * 512 + w * 2 + (k & 1)] =
            *reinterpret_cast<unsigned short*>(&v);
    } else if (idx < T0 + T1) {
        int i2 = idx - T0;
        int k = i2 & 1023, r = (i2 >> 10) & 63, n = i2 >> 16;
        int orow = (r >> 4) * 512 + n * 16 + (r & 15);
        float f = (k < 512) ? Wih1[orow * 512 + k] : Whh1[orow * 512 + (k - 512)];
        int w = (k >> 1) ^ ((r & 7) << 2);
        __nv_bfloat16 v = __float2bfloat16(f);
        g_W1p[(n * 64 + r) * 1024 + w * 2 + (k & 1)] =
            *reinterpret_cast<unsigned short*>(&v);
    } else if (idx < T0 + T1 + 2048) {
        int j = idx - T0 - T1;
        int n = j >> 6, r = j & 63;
        int orow = (r >> 4) * 512 + n * 16 + (r & 15);
        g_b0p[j] = bih0[orow] + bhh0[orow];
        g_b1p[j] = bih1[orow] + bhh1[orow];
    }
}

// ============ init: tanh(c_star @ W^T + b), interleaved reshape ============
// out elem (rb,n): layer=rb/256, b=(rb%256)*2+(n>=512), d=n%512
__global__ void __launch_bounds__(256) init_gemm(const float* __restrict__ cstar,
                                                 const float* __restrict__ Wt,
                                                 const float* __restrict__ bias,
                                                 int is_h) {
    __shared__ float As[64][20];
    __shared__ float Bs[64][20];
    int tid = threadIdx.x;
    int rb0 = blockIdx.x * 64, n0 = blockIdx.y * 64;
    int tx = tid & 15, ty = tid >> 4;
    float acc[4][4];
#pragma unroll
    for (int i = 0; i < 4; i++)
#pragma unroll
        for (int j = 0; j < 4; j++) acc[i][j] = 0.f;
    int lr = tid >> 2, lc = (tid & 3) * 4;
    for (int k0 = 0; k0 < 512; k0 += 16) {
        *(float4*)&As[lr][lc] = *(const float4*)&cstar[(rb0 + lr) * 512 + k0 + lc];
        *(float4*)&Bs[lr][lc] = *(const float4*)&Wt[(n0 + lr) * 512 + k0 + lc];
        __syncthreads();
#pragma unroll
        for (int kk = 0; kk < 16; kk++) {
            float a[4], bv[4];
#pragma unroll
            for (int i = 0; i < 4; i++) a[i] = As[ty + 16 * i][kk];
#pragma unroll
            for (int j = 0; j < 4; j++) bv[j] = Bs[tx + 16 * j][kk];
#pragma unroll
            for (int i = 0; i < 4; i++)
#pragma unroll
                for (int j = 0; j < 4; j++) acc[i][j] += a[i] * bv[j];
        }
        __syncthreads();
    }
#pragma unroll
    for (int i = 0; i < 4; i++)
#pragma unroll
        for (int j = 0; j < 4; j++) {
            int rb = rb0 + ty + 16 * i;
            int n = n0 + tx + 16 * j;
            float v = tanhf(acc[i][j] + bias[n]);
            int b = ((rb & 255) << 1) + (n >> 9);
            int d = n & 511;
            if (is_h) {
                if (rb < 256) g_h0[0][b * 512 + d] = __float2bfloat16(v);
                else          g_A1[0][b * 1024 + 512 + d] = __float2bfloat16(v);
            } else {
                if (rb < 256) g_c0[b * 512 + d] = v;
                else          g_c1[b * 512 + d] = v;
            }
        }
}

__global__ void reset_sync() { g_sync = 0; }

// ============ persistent recurrence ============
__device__ __forceinline__ void grid_sync(unsigned target) {
    __threadfence();
    __syncthreads();
    if (threadIdx.x == 0) {
        atomicAdd(&g_sync, 1u);
        unsigned v;
        do {
            asm volatile("ld.acquire.gpu.global.u32 %0, [%1];" : "=r"(v) : "l"(&g_sync));
        } while (v < target);
    }
    __syncthreads();
}

// C[128x64] = A[128xK] @ W[64xK]^T ; A streamed (cp.async dbl buf), W smem-resident
__device__ __forceinline__ void run_gemm(const __nv_bfloat16* __restrict__ Ag, int K,
                                         char* smem_c, unsigned ab_u, int w_off,
                                         int WRW, int m0, int wm, int wn,
                                         int tid, int lane, float (&acc)[2][4][4]) {
    const int tg = lane & 3, gp = lane >> 2;
    const int NC = K >> 6;
#pragma unroll
    for (int i = 0; i < 2; i++)
#pragma unroll
        for (int j = 0; j < 4; j++)
#pragma unroll
            for (int x = 0; x < 4; x++) acc[i][j][x] = 0.f;

    auto loadA = [&](int kc, int buf) {
#pragma unroll
        for (int i = 0; i < 4; i++) {
            int id = tid + i * 256;
            int r = id >> 3, seg = id & 7;  // 128 rows x 8 segs of 16B
            cpa16(ab_u + buf * 16384 + r * 128 + ((seg ^ (r & 7)) << 4),
                  Ag + (m0 * 128 + r) * K + kc * 64 + seg * 8);
        }
        asm volatile("cp.async.commit_group;");
    };

    loadA(0, 0);
    for (int kc = 0; kc < NC; kc++) {
        if (kc + 1 < NC) {
            loadA(kc + 1, (kc + 1) & 1);
            asm volatile("cp.async.wait_group 1;");
        } else {
            asm volatile("cp.async.wait_group 0;");
        }
        __syncthreads();
        const unsigned* AW = (const unsigned*)(smem_c + AB_OFF + (kc & 1) * 16384);
        const unsigned* WW = (const unsigned*)(smem_c + w_off);
#pragma unroll
        for (int ks = 0; ks < 4; ks++) {
            unsigned a[2][4];
#pragma unroll
            for (int mf = 0; mf < 2; mf++) {
                int ra = wm * 32 + mf * 16 + gp, rb = ra + 8;
                int sw = (ra & 7) << 2;  // (ra&7)==(rb&7)
                int w0i = (ks * 8 + tg) ^ sw;
                int w1i = (ks * 8 + 4 + tg) ^ sw;
                a[mf][0] = AW[ra * 32 + w0i];
                a[mf][1] = AW[rb * 32 + w0i];
                a[mf][2] = AW[ra * 32 + w1i];
                a[mf][3] = AW[rb * 32 + w1i];
            }
#pragma unroll
            for (int nf = 0; nf < 4; nf++) {
                int n = wn * 32 + nf * 8 + gp;
                int swn = (n & 7) << 2;
                int wb = kc * 32 + ks * 8 + tg;
                unsigned b0 = WW[n * WRW + (wb ^ swn)];
                unsigned b1 = WW[n * WRW + ((wb + 4) ^ swn)];
                mma_bf16(acc[0][nf], a[0], b0, b1);
                mma_bf16(acc[1][nf], a[1], b0, b1);
            }
        }
        __syncthreads();
    }
}

__device__ __forceinline__ void epilogue(int layer, int t, int m0, int n0,
                                         float (&acc)[2][4][4], char* smem_c,
                                         int tid, int lane, int wm, int wn) {
    float* Csh = (float*)(smem_c + AB_OFF);  // 128x64, XOR swizzle ((r&7)<<3) on col
    const float* biasS = (const float*)(smem_c + (layer ? B1_OFF : B0_OFF));
    const float* owS = (const float*)(smem_c + OW_OFF);
    int gp = lane >> 2, tg = lane & 3;
#pragma unroll
    for (int mf = 0; mf < 2; mf++)
#pragma unroll
        for (int nf = 0; nf < 4; nf++) {
            int row = wm * 32 + mf * 16 + gp;
            int col = wn * 32 + nf * 8 + tg * 2;
            *(float2*)&Csh[row * 64 + (col ^ ((row & 7) << 3))] =
                make_float2(acc[mf][nf][0], acc[mf][nf][1]);
            int row2 = row + 8;
            *(float2*)&Csh[row2 * 64 + (col ^ ((row2 & 7) << 3))] =
                make_float2(acc[mf][nf][2], acc[mf][nf][3]);
        }
    __syncthreads();

    int r = tid >> 1, d8 = (tid & 1) * 8;
    int b = m0 * 128 + r;
    int sw = (r & 7) << 3;
    float* cg = layer ? g_c1 : g_c0;
    float part = 0.f;
    unsigned short hv[8];
#pragma unroll
    for (int dd = 0; dd < 8; dd++) {
        int d = d8 + dd;
        float iv = Csh[r * 64 + (d ^ sw)] + biasS[d];
        float fv = Csh[r * 64 + ((16 + d) ^ sw)] + biasS[16 + d];
        float gv = Csh[r * 64 + ((32 + d) ^ sw)] + biasS[32 + d];
        float ov = Csh[r * 64 + ((48 + d) ^ sw)] + biasS[48 + d];
        int dg = n0 * 16 + d;
        float co = cg[b * 512 + dg];
        float cn = sigm(fv) * co + sigm(iv) * tanh_(gv);
        float hn = sigm(ov) * tanh_(cn);
        cg[b * 512 + dg] = cn;
        __nv_bfloat16 hb = __float2bfloat16(hn);
        hv[dd] = *reinterpret_cast<unsigned short*>(&hb);
        if (layer == 1) part += hn * owS[d];
    }
    uint4 pk = *reinterpret_cast<uint4*>(hv);
    int dg0 = n0 * 16 + d8;
    if (layer == 0) {
        *(uint4*)&g_h0[(t + 1) & 1][b * 512 + dg0] = pk;   // next layer0 input
        *(uint4*)&g_A1[t & 1][b * 1024 + dg0] = pk;        // y0(t)
    } else {
        *(uint4*)&g_A1[(t + 1) & 1][b * 1024 + 512 + dg0] = pk;  // h1(t)
        part += __shfl_xor_sync(0xffffffffu, part, 1);
        if ((tid & 1) == 0) g_Opart[(t * 32 + n0) * 512 + b] = part;
    }
    __syncthreads();  // Csh region becomes A buffers again
}

__global__ void __launch_bounds__(256, 1) lstm_persist(const float* __restrict__ ow_g) {
    extern __shared__ char smem_c[];
    const int tid = threadIdx.x, lane = tid & 31, wid = tid >> 5;
    const int bid = blockIdx.x;
    const int m0 = bid >> 5, n0 = bid & 31;
    const int wm = wid & 3, wn = wid >> 2;
    unsigned smem_u = (unsigned)__cvta_generic_to_shared(smem_c);
    unsigned ab_u = smem_u + AB_OFF;

    // stage this block's weight slices (already packed+swizzled in global)
    {
        const unsigned short* s0 = g_W0p + n0 * (64 * 512);
        for (int i = tid; i < 4096; i += 256) cpa16(smem_u + i * 16, s0 + i * 8);
        const unsigned short* s1 = g_W1p + n0 * (64 * 1024);
        for (int i = tid; i < 8192; i += 256) cpa16(smem_u + W1_OFF + i * 16, s1 + i * 8);
        asm volatile("cp.async.commit_group;");
        float* bS = (float*)(smem_c + B0_OFF);
        if (tid < 64) {
            bS[tid] = g_b0p[n0 * 64 + tid];
            bS[64 + tid] = g_b1p[n0 * 64 + tid];
        }
        if (tid < 16) ((float*)(smem_c + OW_OFF))[tid] = ow_g[n0 * 16 + tid];
        asm volatile("cp.async.wait_group 0;");
        __syncthreads();
    }

    float acc[2][4][4];
    // phase p: layer0(t=p) for p<256 ; layer1(t=p-1) for p>=1 ; 1 grid sync each
    for (int p = 0; p <= 256; p++) {
        if (p < 256) {
            run_gemm(g_h0[p & 1], 512, smem_c, ab_u, 0, 256,
                     m0, wm, wn, tid, lane, acc);
            epilogue(0, p, m0, n0, acc, smem_c, tid, lane, wm, wn);
        }
        if (p >= 1) {
            run_gemm(g_A1[(p - 1) & 1], 1024, smem_c, ab_u, W1_OFF, 512,
                     m0, wm, wn, tid, lane, acc);
            epilogue(1, p - 1, m0, n0, acc, smem_c, tid, lane, wm, wn);
        }
        grid_sync((unsigned)(p + 1) * gridDim.x);
    }
}

// ============ final projection reduce + layout ============
__global__ void final_proj(const float* __restrict__ out_b, float* __restrict__ out) {
    int idx = blockIdx.x * blockDim.x + threadIdx.x;
    if (idx >= 512 * 256) return;
    int t = idx >> 9, b = idx & 511;
    float s = out_b[0];
#pragma unroll
    for (int j = 0; j < 32; j++) s += g_Opart[(t * 32 + j) * 512 + b];
    if (t < 255) out[b * 255 + t] = s;     // recon (B, L-1)
    else         out[512 * 255 + b] = s;   // pred (B,)
}

// ============ launch ============
extern "C" void kernel_launch(void* const* d_in, const int* in_sizes, int n_in,
                              void* d_out, int out_size) {
    (void)in_sizes; (void)n_in; (void)out_size;
    const float* c_star   = (const float*)d_in[0];
    const float* init_h_w = (const float*)d_in[1];
    const float* init_h_b = (const float*)d_in[2];
    const float* init_c_w = (const float*)d_in[3];
    const float* init_c_b = (const float*)d_in[4];
    // d_in[5] = W_ih0: unused (layer0 input term is pure bias)
    const float* W_hh0 = (const float*)d_in[6];
    const float* b_ih0 = (const float*)d_in[7];
    const float* b_hh0 = (const float*)d_in[8];
    const float* W_ih1 = (const float*)d_in[9];
    const float* W_hh1 = (const float*)d_in[10];
    const float* b_ih1 = (const float*)d_in[11];
    const float* b_hh1 = (const float*)d_in[12];
    const float* out_w = (const float*)d_in[13];
    const float* out_b = (const float*)d_in[14];
    float* out = (float*)d_out;

    static bool attr_set = false;
    if (!attr_set) {
        cudaFuncSetAttribute(lstm_persist,
                             cudaFuncAttributeMaxDynamicSharedMemorySize, SMEM_BYTES);
        attr_set = true;
    }

    pack_weights<<<12296, 256>>>(W_hh0, W_ih1, W_hh1, b_ih0, b_hh0, b_ih1, b_hh1);
    dim3 ig(8, 16);
    init_gemm<<<ig, 256>>>(c_star, init_h_w, init_h_b, 1);
    init_gemm<<<ig, 256>>>(c_star, init_c_w, init_c_b, 0);
    reset_sync<<<1, 1>>>();
    lstm_persist<<<128, 256, SMEM_BYTES>>>(out_w);
    final_proj<<<512, 256>>>(out_b, out);
}

// round 14
// speedup vs baseline: 3.1061x; 1.2851x over previous
#include <cuda_runtime.h>
#include <cuda_bf16.h>

// ============ sizes ============
// B=512, D=512, L=256, 2 layers. Persistent kernel: 128 blocks x 256 thr,
// block (m0=bid>>5, n0=bid&31): 128 batch rows x 16 d (= 64 packed gate rows).

// smem layout (bytes)
static constexpr int SMEM_BYTES = 230400;
static constexpr int W1_OFF = 65536;    // W0: [0,65536)  64x512 bf16 swizzled
static constexpr int AB_OFF = 196608;   // W1: [65536,196608) 64x1024 bf16
static constexpr int B0_OFF = 229376;   // A dbl buf 2x16384 / C staging 128x64 f32
static constexpr int B1_OFF = 229632;
static constexpr int OW_OFF = 229888;

// ============ device scratch ============
__device__ __nv_bfloat16 g_h0[2][512 * 512];
__device__ __nv_bfloat16 g_A1[2][512 * 1024];   // [y0 | h1]
__device__ float g_c0[512 * 512];
__device__ float g_c1[512 * 512];
__device__ unsigned short g_W0p[32 * 64 * 512];
__device__ unsigned short g_W1p[32 * 64 * 1024];
__device__ float g_b0p[2048];
__device__ float g_b1p[2048];
__device__ float g_Opart[256 * 32 * 512];
__device__ unsigned g_sync;

__device__ __forceinline__ float tanhax(float x) {
    float r;
    asm("tanh.approx.f32 %0, %1;" : "=f"(r) : "f"(x));
    return r;
}
__device__ __forceinline__ float sigax(float x) {
    return fmaf(tanhax(0.5f * x), 0.5f, 0.5f);
}
__device__ __forceinline__ void cpa16(unsigned dst_s, const void* src_g) {
    asm volatile("cp.async.cg.shared.global [%0], [%1], 16;" :: "r"(dst_s), "l"(src_g));
}
__device__ __forceinline__ void mma_bf16(float* c, const unsigned* a,
                                         unsigned b0, unsigned b1) {
    asm volatile(
        "mma.sync.aligned.m16n8k16.row.col.f32.bf16.bf16.f32 "
        "{%0,%1,%2,%3},{%4,%5,%6,%7},{%8,%9},{%0,%1,%2,%3};"
        : "+f"(c[0]), "+f"(c[1]), "+f"(c[2]), "+f"(c[3])
        : "r"(a[0]), "r"(a[1]), "r"(a[2]), "r"(a[3]), "r"(b0), "r"(b1));
}
__device__ __forceinline__ void ldsm4(unsigned* r, unsigned addr) {
    asm volatile("ldmatrix.sync.aligned.m8n8.x4.shared.b16 {%0,%1,%2,%3}, [%4];"
                 : "=r"(r[0]), "=r"(r[1]), "=r"(r[2]), "=r"(r[3]) : "r"(addr));
}

// ============ weight pack: bf16 + block layout + XOR swizzle ============
// block n (0..31), packed row r (0..63): orig gate row = (r>>4)*512 + n*16 + (r&15).
// bf16 pair-word w (k>>1) stored at w ^ ((r&7)<<2)  == 16B seg (k>>3) ^ (r&7).
__global__ void pack_weights(const float* __restrict__ Whh0,
                             const float* __restrict__ Wih1,
                             const float* __restrict__ Whh1,
                             const float* __restrict__ bih0,
                             const float* __restrict__ bhh0,
                             const float* __restrict__ bih1,
                             const float* __restrict__ bhh1) {
    int idx = blockIdx.x * blockDim.x + threadIdx.x;
    const int T0 = 32 * 64 * 512;
    const int T1 = 32 * 64 * 1024;
    if (idx < T0) {
        int k = idx & 511, r = (idx >> 9) & 63, n = idx >> 15;
        int orow = (r >> 4) * 512 + n * 16 + (r & 15);
        int w = (k >> 1) ^ ((r & 7) << 2);
        __nv_bfloat16 v = __float2bfloat16(Whh0[orow * 512 + k]);
        g_W0p[(n * 64 + r) * 512 + w * 2 + (k & 1)] =
            *reinterpret_cast<unsigned short*>(&v);
    } else if (idx < T0 + T1) {
        int i2 = idx - T0;
        int k = i2 & 1023, r = (i2 >> 10) & 63, n = i2 >> 16;
        int orow = (r >> 4) * 512 + n * 16 + (r & 15);
        float f = (k < 512) ? Wih1[orow * 512 + k] : Whh1[orow * 512 + (k - 512)];
        int w = (k >> 1) ^ ((r & 7) << 2);
        __nv_bfloat16 v = __float2bfloat16(f);
        g_W1p[(n * 64 + r) * 1024 + w * 2 + (k & 1)] =
            *reinterpret_cast<unsigned short*>(&v);
    } else if (idx < T0 + T1 + 2048) {
        int j = idx - T0 - T1;
        int n = j >> 6, r = j & 63;
        int orow = (r >> 4) * 512 + n * 16 + (r & 15);
        g_b0p[j] = bih0[orow] + bhh0[orow];
        g_b1p[j] = bih1[orow] + bhh1[orow];
    }
}

// ============ init: tanh(c_star @ W^T + b), interleaved reshape ============
// out elem (rb,n): layer=rb/256, b=(rb%256)*2+(n>=512), d=n%512
__global__ void __launch_bounds__(256) init_gemm(const float* __restrict__ cstar,
                                                 const float* __restrict__ Wt,
                                                 const float* __restrict__ bias,
                                                 int is_h) {
    __shared__ float As[64][20];
    __shared__ float Bs[64][20];
    int tid = threadIdx.x;
    int rb0 = blockIdx.x * 64, n0 = blockIdx.y * 64;
    int tx = tid & 15, ty = tid >> 4;
    float acc[4][4];
#pragma unroll
    for (int i = 0; i < 4; i++)
#pragma unroll
        for (int j = 0; j < 4; j++) acc[i][j] = 0.f;
    int lr = tid >> 2, lc = (tid & 3) * 4;
    for (int k0 = 0; k0 < 512; k0 += 16) {
        *(float4*)&As[lr][lc] = *(const float4*)&cstar[(rb0 + lr) * 512 + k0 + lc];
        *(float4*)&Bs[lr][lc] = *(const float4*)&Wt[(n0 + lr) * 512 + k0 + lc];
        __syncthreads();
#pragma unroll
        for (int kk = 0; kk < 16; kk++) {
            float a[4], bv[4];
#pragma unroll
            for (int i = 0; i < 4; i++) a[i] = As[ty + 16 * i][kk];
#pragma unroll
            for (int j = 0; j < 4; j++) bv[j] = Bs[tx + 16 * j][kk];
#pragma unroll
            for (int i = 0; i < 4; i++)
#pragma unroll
                for (int j = 0; j < 4; j++) acc[i][j] += a[i] * bv[j];
        }
        __syncthreads();
    }
#pragma unroll
    for (int i = 0; i < 4; i++)
#pragma unroll
        for (int j = 0; j < 4; j++) {
            int rb = rb0 + ty + 16 * i;
            int n = n0 + tx + 16 * j;
            float v = tanhf(acc[i][j] + bias[n]);
            int b = ((rb & 255) << 1) + (n >> 9);
            int d = n & 511;
            if (is_h) {
                if (rb < 256) g_h0[0][b * 512 + d] = __float2bfloat16(v);
                else          g_A1[0][b * 1024 + 512 + d] = __float2bfloat16(v);
            } else {
                if (rb < 256) g_c0[b * 512 + d] = v;
                else          g_c1[b * 512 + d] = v;
            }
        }
}

__global__ void reset_sync() { g_sync = 0; }

// ============ persistent recurrence ============
__device__ __forceinline__ void grid_sync(unsigned target) {
    __threadfence();
    __syncthreads();
    if (threadIdx.x == 0) {
        atomicAdd(&g_sync, 1u);
        unsigned v;
        do {
            asm volatile("ld.acquire.gpu.global.u32 %0, [%1];" : "=r"(v) : "l"(&g_sync));
        } while (v < target);
    }
    __syncthreads();
}

// C[128x64] = A[128xK] @ W[64xK]^T ; A streamed (cp.async dbl buf), W smem-resident
template <int K>
__device__ __forceinline__ void run_gemm(const __nv_bfloat16* __restrict__ Ag,
                                         char* smem_c, unsigned ab_u, unsigned w_u,
                                         int m0, int wm, int wn, int tid, int lane,
                                         float (&acc)[2][4][4]) {
    const int NC = K >> 6;
    const int RB = K * 2;  // W row bytes in smem
#pragma unroll
    for (int i = 0; i < 2; i++)
#pragma unroll
        for (int j = 0; j < 4; j++)
#pragma unroll
            for (int x = 0; x < 4; x++) acc[i][j][x] = 0.f;

    // ldmatrix lane geometry
    const int l7 = lane & 7;
    const int aR0 = wm * 32 + l7 + ((lane >> 3) & 1) * 8;  // + mf*16
    const int aKs = lane >> 4;                             // k-seg parity for A
    const int bR0 = wn * 32 + l7 + (lane >> 4) * 8;        // + p*16
    const int bKs = (lane >> 3) & 1;                       // k-seg parity for B

    auto loadA = [&](int kc, int buf) {
#pragma unroll
        for (int i = 0; i < 4; i++) {
            int id = tid + i * 256;
            int r = id >> 3, seg = id & 7;  // 128 rows x 8 segs of 16B
            cpa16(ab_u + buf * 16384 + r * 128 + ((seg ^ (r & 7)) << 4),
                  Ag + (m0 * 128 + r) * K + kc * 64 + seg * 8);
        }
        asm volatile("cp.async.commit_group;");
    };

    loadA(0, 0);
    for (int kc = 0; kc < NC; kc++) {
        if (kc + 1 < NC) {
            loadA(kc + 1, (kc + 1) & 1);
            asm volatile("cp.async.wait_group 1;");
        } else {
            asm volatile("cp.async.wait_group 0;");
        }
        __syncthreads();
        unsigned abase = ab_u + (kc & 1) * 16384;
#pragma unroll
        for (int ks = 0; ks < 4; ks++) {
            unsigned a0[4], a1[4], bA[4], bB[4];
            {
                int r = aR0;
                ldsm4(a0, abase + r * 128 + (((ks * 2 + aKs) ^ (r & 7)) << 4));
                r = aR0 + 16;
                ldsm4(a1, abase + r * 128 + (((ks * 2 + aKs) ^ (r & 7)) << 4));
                int kg = kc * 8 + ks * 2 + bKs;
                r = bR0;
                ldsm4(bA, w_u + r * RB + ((kg ^ (r & 7)) << 4));
                r = bR0 + 16;
                ldsm4(bB, w_u + r * RB + ((kg ^ (r & 7)) << 4));
            }
            mma_bf16(acc[0][0], a0, bA[0], bA[1]);
            mma_bf16(acc[1][0], a1, bA[0], bA[1]);
            mma_bf16(acc[0][1], a0, bA[2], bA[3]);
            mma_bf16(acc[1][1], a1, bA[2], bA[3]);
            mma_bf16(acc[0][2], a0, bB[0], bB[1]);
            mma_bf16(acc[1][2], a1, bB[0], bB[1]);
            mma_bf16(acc[0][3], a0, bB[2], bB[3]);
            mma_bf16(acc[1][3], a1, bB[2], bB[3]);
        }
        __syncthreads();
    }
}

__device__ __forceinline__ void epilogue(int layer, int t, int m0, int n0,
                                         float (&acc)[2][4][4], char* smem_c,
                                         int tid, int lane, int wm, int wn,
                                         float* creg) {
    float* Csh = (float*)(smem_c + AB_OFF);  // 128x64, XOR swizzle ((r&7)<<3) on col
    const float* biasS = (const float*)(smem_c + (layer ? B1_OFF : B0_OFF));
    const float* owS = (const float*)(smem_c + OW_OFF);
    int gp = lane >> 2, tg = lane & 3;
#pragma unroll
    for (int mf = 0; mf < 2; mf++)
#pragma unroll
        for (int nf = 0; nf < 4; nf++) {
            int row = wm * 32 + mf * 16 + gp;
            int col = wn * 32 + nf * 8 + tg * 2;
            *(float2*)&Csh[row * 64 + (col ^ ((row & 7) << 3))] =
                make_float2(acc[mf][nf][0], acc[mf][nf][1]);
            int row2 = row + 8;
            *(float2*)&Csh[row2 * 64 + (col ^ ((row2 & 7) << 3))] =
                make_float2(acc[mf][nf][2], acc[mf][nf][3]);
        }
    __syncthreads();

    int r = tid >> 1, d8 = (tid & 1) * 8;
    int b = m0 * 128 + r;
    int sw = (r & 7) << 3;
    float part = 0.f;
    unsigned short hv[8];
#pragma unroll
    for (int dd = 0; dd < 8; dd++) {
        int d = d8 + dd;
        float iv = Csh[r * 64 + (d ^ sw)] + biasS[d];
        float fv = Csh[r * 64 + ((16 + d) ^ sw)] + biasS[16 + d];
        float gv = Csh[r * 64 + ((32 + d) ^ sw)] + biasS[32 + d];
        float ov = Csh[r * 64 + ((48 + d) ^ sw)] + biasS[48 + d];
        float co = creg[dd];
        float cn = sigax(fv) * co + sigax(iv) * tanhax(gv);
        float hn = sigax(ov) * tanhax(cn);
        creg[dd] = cn;
        __nv_bfloat16 hb = __float2bfloat16(hn);
        hv[dd] = *reinterpret_cast<unsigned short*>(&hb);
        if (layer == 1) part += hn * owS[d];
    }
    uint4 pk = *reinterpret_cast<uint4*>(hv);
    int dg0 = n0 * 16 + d8;
    if (layer == 0) {
        *(uint4*)&g_h0[(t + 1) & 1][b * 512 + dg0] = pk;   // next layer0 input
        *(uint4*)&g_A1[t & 1][b * 1024 + dg0] = pk;        // y0(t)
    } else {
        *(uint4*)&g_A1[(t + 1) & 1][b * 1024 + 512 + dg0] = pk;  // h1(t)
        part += __shfl_xor_sync(0xffffffffu, part, 1);
        if ((tid & 1) == 0) g_Opart[(t * 32 + n0) * 512 + b] = part;
    }
    __syncthreads();  // Csh region becomes A buffers again
}

__global__ void __launch_bounds__(256, 1) lstm_persist(const float* __restrict__ ow_g) {
    extern __shared__ char smem_c[];
    const int tid = threadIdx.x, lane = tid & 31, wid = tid >> 5;
    const int bid = blockIdx.x;
    const int m0 = bid >> 5, n0 = bid & 31;
    const int wm = wid & 3, wn = wid >> 2;
    unsigned smem_u = (unsigned)__cvta_generic_to_shared(smem_c);
    unsigned ab_u = smem_u + AB_OFF;

    // stage this block's weight slices (already packed+swizzled in global)
    {
        const unsigned short* s0 = g_W0p + n0 * (64 * 512);
        for (int i = tid; i < 4096; i += 256) cpa16(smem_u + i * 16, s0 + i * 8);
        const unsigned short* s1 = g_W1p + n0 * (64 * 1024);
        for (int i = tid; i < 8192; i += 256) cpa16(smem_u + W1_OFF + i * 16, s1 + i * 8);
        asm volatile("cp.async.commit_group;");
        float* bS = (float*)(smem_c + B0_OFF);
        if (tid < 64) {
            bS[tid] = g_b0p[n0 * 64 + tid];
            bS[64 + tid] = g_b1p[n0 * 64 + tid];
        }
        if (tid < 16) ((float*)(smem_c + OW_OFF))[tid] = ow_g[n0 * 16 + tid];
        asm volatile("cp.async.wait_group 0;");
        __syncthreads();
    }

    // cell state lives in registers: this thread owns (b = m0*128 + tid/2,
    // d = n0*16 + (tid&1)*8 .. +8) in the epilogue, every phase.
    float c0r[8], c1r[8];
    {
        int er = tid >> 1, ed0 = n0 * 16 + (tid & 1) * 8;
        int eb = m0 * 128 + er;
#pragma unroll
        for (int dd = 0; dd < 8; dd++) {
            c0r[dd] = g_c0[eb * 512 + ed0 + dd];
            c1r[dd] = g_c1[eb * 512 + ed0 + dd];
        }
    }

    float acc[2][4][4];
    // phase p: layer0(t=p) for p<256 ; layer1(t=p-1) for p>=1 ; 1 grid sync each
    for (int p = 0; p <= 256; p++) {
        if (p < 256) {
            run_gemm<512>(g_h0[p & 1], smem_c, ab_u, smem_u,
                          m0, wm, wn, tid, lane, acc);
            epilogue(0, p, m0, n0, acc, smem_c, tid, lane, wm, wn, c0r);
        }
        if (p >= 1) {
            run_gemm<1024>(g_A1[(p - 1) & 1], smem_c, ab_u, smem_u + W1_OFF,
                           m0, wm, wn, tid, lane, acc);
            epilogue(1, p - 1, m0, n0, acc, smem_c, tid, lane, wm, wn, c1r);
        }
        grid_sync((unsigned)(p + 1) * gridDim.x);
    }
}

// ============ final projection reduce + layout ============
__global__ void final_proj(const float* __restrict__ out_b, float* __restrict__ out) {
    int idx = blockIdx.x * blockDim.x + threadIdx.x;
    if (idx >= 512 * 256) return;
    int t = idx >> 9, b = idx & 511;
    float s = out_b[0];
#pragma unroll
    for (int j = 0; j < 32; j++) s += g_Opart[(t * 32 + j) * 512 + b];
    if (t < 255) out[b * 255 + t] = s;     // recon (B, L-1)
    else         out[512 * 255 + b] = s;   // pred (B,)
}

// ============ launch ============
extern "C" void kernel_launch(void* const* d_in, const int* in_sizes, int n_in,
                              void* d_out, int out_size) {
    (void)in_sizes; (void)n_in; (void)out_size;
    const float* c_star   = (const float*)d_in[0];
    const float* init_h_w = (const float*)d_in[1];
    const float* init_h_b = (const float*)d_in[2];
    const float* init_c_w = (const float*)d_in[3];
    const float* init_c_b = (const float*)d_in[4];
    // d_in[5] = W_ih0: unused (layer0 input term is pure bias)
    const float* W_hh0 = (const float*)d_in[6];
    const float* b_ih0 = (const float*)d_in[7];
    const float* b_hh0 = (const float*)d_in[8];
    const float* W_ih1 = (const float*)d_in[9];
    const float* W_hh1 = (const float*)d_in[10];
    const float* b_ih1 = (const float*)d_in[11];
    const float* b_hh1 = (const float*)d_in[12];
    const float* out_w = (const float*)d_in[13];
    const float* out_b = (const float*)d_in[14];
    float* out = (float*)d_out;

    static bool attr_set = false;
    if (!attr_set) {
        cudaFuncSetAttribute(lstm_persist,
                             cudaFuncAttributeMaxDynamicSharedMemorySize, SMEM_BYTES);
        attr_set = true;
    }

    pack_weights<<<12296, 256>>>(W_hh0, W_ih1, W_hh1, b_ih0, b_hh0, b_ih1, b_hh1);
    dim3 ig(8, 16);
    init_gemm<<<ig, 256>>>(c_star, init_h_w, init_h_b, 1);
    init_gemm<<<ig, 256>>>(c_star, init_c_w, init_c_b, 0);
    reset_sync<<<1, 1>>>();
    lstm_persist<<<128, 256, SMEM_BYTES>>>(out_w);
    final_proj<<<512, 256>>>(out_b, out);
}